// round 4
// baseline (speedup 1.0000x reference)
#include <cuda_runtime.h>
#include <cuda_bf16.h>
#include <math.h>

// Problem constants
#define B_   2048
#define TIN  365
#define CIN0 4
#define KPROT 32
#define LOUT_ 366
#define LSTR_ 368   // padded time stride (16B aligned rows)

// ---------------- scratch (device globals; no allocs allowed) ----------------
__device__ float  g_y1[2048ull*128*LSTR_];   // conv1 pre-BN output
__device__ float  g_y2[2048ull*256*LSTR_];   // conv2 pre-BN output
__device__ float  g_y3[2048ull*128*LSTR_];   // conv3 pre-BN output
__device__ float  g_w1r[128*4*8];
__device__ float  g_w2r[256*128*5];
__device__ float  g_w3r[128*256*3];
__device__ double g_sum[512];                // [0,128) L1, [128,384) L2, [384,512) L3
__device__ double g_sq [512];
__device__ float  g_bnS[512];
__device__ float  g_bnT[512];
__device__ float  g_off[2048*128];           // tanh offsets (B, K*C)

// ---------------- small kernels ----------------
__global__ void zero_stats(double* s, double* q) {
    int i = blockIdx.x * 256 + threadIdx.x;
    if (i < 512) { s[i] = 0.0; q[i] = 0.0; }
}

// (CO,CI,KW) -> [(ci*KW+k)*CO + co]
__global__ void reorder_w(const float* __restrict__ w, float* __restrict__ wr,
                          int CO, int CI, int KW) {
    int idx = blockIdx.x * 256 + threadIdx.x;
    int n = CO * CI * KW;
    if (idx < n) {
        int k  = idx % KW;
        int r  = idx / KW;
        int ci = r % CI;
        int co = r / CI;
        wr[((size_t)ci * KW + k) * CO + co] = w[idx];
    }
}

__global__ void finalize_bn(const double* __restrict__ sum, const double* __restrict__ sq,
                            const float* __restrict__ g, const float* __restrict__ be,
                            float* __restrict__ S, float* __restrict__ T,
                            int C, double invN) {
    int c = threadIdx.x + blockIdx.x * blockDim.x;
    if (c < C) {
        double mu  = sum[c] * invN;
        double var = sq[c] * invN - mu * mu;
        double s   = (double)g[c] * rsqrt(var + 1e-5);
        S[c] = (float)s;
        T[c] = be[c] - (float)(mu * s);
    }
}

// ---------------- conv + (input BN/ReLU) + bias + stats ----------------
// out[b,co,t] = bias[co] + sum_{ci,k} w[co,ci,k] * a(b,ci,t+k-PAD)
// a = input_seq (FIRST) or relu(bnS*y + bnT)
template<bool FIRST, int CIN, int COUT, int KW, int PAD, int CK>
__global__ __launch_bounds__(256, 2)
void conv_bn(const float* __restrict__ in, const float* __restrict__ wre,
             const float* __restrict__ bias,
             const float* __restrict__ bnS, const float* __restrict__ bnT,
             float* __restrict__ out,
             double* __restrict__ gsum, double* __restrict__ gsq,
             int LIN, int INSTR, int LOUT, int OUTSTR) {
    constexpr int COT = 128;
    constexpr int TT  = 128;
    constexpr int W   = TT + KW - 1;
    constexpr int WS  = ((W + 4 + 3) / 4) * 4;    // padded row stride
    constexpr int NA  = ((8 + KW - 1 + 3) / 4) * 4;

    __shared__ float As[CK][WS];
    __shared__ float Ws[CK][KW][COT];
    __shared__ float sSum[COT];
    __shared__ float sSq[COT];

    const int t0  = blockIdx.x * TT;
    const int co0 = blockIdx.y * COT;
    const int b   = blockIdx.z;
    const int tid = threadIdx.x;
    const int tc  = tid & 15;   // co group
    const int tr  = tid >> 4;   // t group

    for (int i = tid; i < COT; i += 256) { sSum[i] = 0.f; sSq[i] = 0.f; }

    float acc[8][8];
#pragma unroll
    for (int j = 0; j < 8; j++)
#pragma unroll
        for (int i = 0; i < 8; i++) acc[j][i] = 0.f;

    for (int ci0 = 0; ci0 < CIN; ci0 += CK) {
        __syncthreads();
        // load A tile (BN+ReLU applied here for non-first layers)
        for (int idx = tid; idx < CK * W; idx += 256) {
            int ci = idx / W, col = idx % W;
            int tg = t0 - PAD + col;
            float v = 0.f;
            if (tg >= 0 && tg < LIN) {
                if (FIRST) {
                    v = in[((size_t)b * LIN + tg) * CIN + (ci0 + ci)];
                } else {
                    v = in[((size_t)b * CIN + ci0 + ci) * INSTR + tg];
                    v = fmaxf(fmaf(bnS[ci0 + ci], v, bnT[ci0 + ci]), 0.f);
                }
            }
            As[ci][col] = v;
        }
        // load W tile (pre-reordered: [(ci*KW+k)*COUT + co])
        for (int idx = tid; idx < CK * KW * COT; idx += 256) {
            int co = idx & (COT - 1);
            int r  = idx >> 7;
            int k  = r % KW;
            int ci = r / KW;
            Ws[ci][k][co] = wre[((size_t)(ci0 + ci) * KW + k) * COUT + co0 + co];
        }
        __syncthreads();
#pragma unroll 1
        for (int ci = 0; ci < CK; ci++) {
            float a[NA];
#pragma unroll
            for (int q = 0; q < NA / 4; q++)
                *(float4*)&a[4 * q] = *(const float4*)&As[ci][tr * 8 + 4 * q];
#pragma unroll
            for (int k = 0; k < KW; k++) {
                float wv[8];
                *(float4*)&wv[0] = *(const float4*)&Ws[ci][k][tc * 8];
                *(float4*)&wv[4] = *(const float4*)&Ws[ci][k][tc * 8 + 4];
#pragma unroll
                for (int j = 0; j < 8; j++)
#pragma unroll
                    for (int i = 0; i < 8; i++)
                        acc[j][i] = fmaf(wv[j], a[k + i], acc[j][i]);
            }
        }
    }

    // bias + per-channel stats (only valid t)
    const bool fullT = (t0 + TT <= LOUT);
    float bj[8];
#pragma unroll
    for (int j = 0; j < 8; j++) bj[j] = bias[co0 + tc * 8 + j];
#pragma unroll
    for (int j = 0; j < 8; j++) {
        float s = 0.f, s2 = 0.f;
#pragma unroll
        for (int i = 0; i < 8; i++) {
            float v = acc[j][i] + bj[j];
            acc[j][i] = v;
            if (fullT || (t0 + tr * 8 + i < LOUT)) { s += v; s2 += v * v; }
        }
        atomicAdd(&sSum[tc * 8 + j], s);
        atomicAdd(&sSq[tc * 8 + j], s2);
    }
    // store
#pragma unroll
    for (int j = 0; j < 8; j++) {
        size_t base = ((size_t)b * COUT + co0 + tc * 8 + j) * OUTSTR + t0 + tr * 8;
        if (fullT) {
            *(float4*)&out[base]     = make_float4(acc[j][0], acc[j][1], acc[j][2], acc[j][3]);
            *(float4*)&out[base + 4] = make_float4(acc[j][4], acc[j][5], acc[j][6], acc[j][7]);
        } else {
#pragma unroll
            for (int i = 0; i < 8; i++)
                if (t0 + tr * 8 + i < LOUT) out[base + i] = acc[j][i];
        }
    }
    __syncthreads();
    for (int c = tid; c < COT; c += 256) {
        atomicAdd(&gsum[co0 + c], (double)sSum[c]);
        atomicAdd(&gsq[co0 + c],  (double)sSq[c]);
    }
}

// ---------------- pool + fc + offset head ----------------
__global__ void pool_fc_off(const float* __restrict__ y3,
                            const float* __restrict__ s3, const float* __restrict__ t3,
                            const float* __restrict__ fcw, const float* __restrict__ fcb,
                            const float* __restrict__ offw, const float* __restrict__ offb,
                            float* __restrict__ goff) {
    int b = blockIdx.x;
    int c = threadIdx.x;   // 128 threads
    __shared__ float pooled[128];
    __shared__ float feat[128];

    const float* row = y3 + ((size_t)b * 128 + c) * LSTR_;
    float s = s3[c], t = t3[c], acc = 0.f;
    int i = 0;
    for (; i + 4 <= LOUT_; i += 4) {
        float4 v = *(const float4*)&row[i];
        acc += fmaxf(fmaf(s, v.x, t), 0.f) + fmaxf(fmaf(s, v.y, t), 0.f)
             + fmaxf(fmaf(s, v.z, t), 0.f) + fmaxf(fmaf(s, v.w, t), 0.f);
    }
    for (; i < LOUT_; i++) acc += fmaxf(fmaf(s, row[i], t), 0.f);
    pooled[c] = acc * (1.f / (float)LOUT_);
    __syncthreads();

    float f = fcb[c];
#pragma unroll 4
    for (int q = 0; q < 32; q++) {
        float4 w = *(const float4*)&fcw[c * 128 + 4 * q];
        float4 p = *(const float4*)&pooled[4 * q];
        f = fmaf(w.x, p.x, f); f = fmaf(w.y, p.y, f);
        f = fmaf(w.z, p.z, f); f = fmaf(w.w, p.w, f);
    }
    feat[c] = f;
    __syncthreads();

    float o = offb[c];
#pragma unroll 4
    for (int q = 0; q < 32; q++) {
        float4 w = *(const float4*)&offw[c * 128 + 4 * q];
        float4 p = *(const float4*)&feat[4 * q];
        o = fmaf(w.x, p.x, o); o = fmaf(w.y, p.y, o);
        o = fmaf(w.z, p.z, o); o = fmaf(w.w, p.w, o);
    }
    goff[(size_t)b * 128 + c] = tanhf(o);
}

// ---------------- distances + argmin + gather output ----------------
__global__ void dist_out(const float* __restrict__ x, const float* __restrict__ mask,
                         const float* __restrict__ protos, const float* __restrict__ goff,
                         float* __restrict__ out) {
    int b = blockIdx.x, tid = threadIdx.x;   // 256 threads
    __shared__ float4 xs[TIN];
    __shared__ float  ms[TIN];
    __shared__ float  sdist[KPROT];
    __shared__ int    sbest;

    for (int t = tid; t < TIN; t += 256) {
        xs[t] = *(const float4*)&x[((size_t)b * TIN + t) * 4];
        ms[t] = mask[(size_t)b * TIN + t];
    }
    if (tid < KPROT) sdist[tid] = 0.f;
    __syncthreads();

    for (int k = 0; k < KPROT; k++) {
        float4 ov = *(const float4*)&goff[(size_t)b * 128 + k * 4];
        float local = 0.f;
        for (int t = tid; t < TIN; t += 256) {
            float4 p  = *(const float4*)&protos[((size_t)k * TIN + t) * 4];
            float4 xv = xs[t];
            float d0 = xv.x - p.x - ov.x;
            float d1 = xv.y - p.y - ov.y;
            float d2 = xv.z - p.z - ov.z;
            float d3 = xv.w - p.w - ov.w;
            local += ms[t] * (d0 * d0 + d1 * d1 + d2 * d2 + d3 * d3);
        }
#pragma unroll
        for (int o = 16; o; o >>= 1) local += __shfl_xor_sync(0xffffffffu, local, o);
        if ((tid & 31) == 0) atomicAdd(&sdist[k], local);
    }
    __syncthreads();
    if (tid < 32) {
        float v = sdist[tid];
        int  idx = tid;
#pragma unroll
        for (int o = 16; o; o >>= 1) {
            float v2 = __shfl_xor_sync(0xffffffffu, v, o);
            int  i2  = __shfl_xor_sync(0xffffffffu, idx, o);
            if (v2 < v || (v2 == v && i2 < idx)) { v = v2; idx = i2; }
        }
        if (tid == 0) sbest = idx;
    }
    __syncthreads();
    int best = sbest;
    float4 ob = *(const float4*)&goff[(size_t)b * 128 + best * 4];
    for (int t = tid; t < TIN; t += 256) {
        float4 p = *(const float4*)&protos[((size_t)best * TIN + t) * 4];
        *(float4*)&out[((size_t)b * TIN + t) * 4] =
            make_float4(p.x + ob.x, p.y + ob.y, p.z + ob.z, p.w + ob.w);
    }
}

// ---------------- launcher ----------------
extern "C" void kernel_launch(void* const* d_in, const int* in_sizes, int n_in,
                              void* d_out, int out_size) {
    (void)in_sizes; (void)n_in; (void)out_size;
    const float* x      = (const float*)d_in[0];
    const float* mask   = (const float*)d_in[2];
    const float* protos = (const float*)d_in[3];
    const float* w1  = (const float*)d_in[4];
    const float* b1  = (const float*)d_in[5];
    const float* g1  = (const float*)d_in[6];
    const float* be1 = (const float*)d_in[7];
    const float* w2  = (const float*)d_in[8];
    const float* b2  = (const float*)d_in[9];
    const float* g2  = (const float*)d_in[10];
    const float* be2 = (const float*)d_in[11];
    const float* w3  = (const float*)d_in[12];
    const float* b3  = (const float*)d_in[13];
    const float* g3  = (const float*)d_in[14];
    const float* be3 = (const float*)d_in[15];
    const float* fcw = (const float*)d_in[16];
    const float* fcb = (const float*)d_in[17];
    const float* offw = (const float*)d_in[18];
    const float* offb = (const float*)d_in[19];
    float* out = (float*)d_out;

    float *y1, *y2, *y3, *w1r, *w2r, *w3r, *bnS, *bnT, *goff;
    double *gsum, *gsq;
    cudaGetSymbolAddress((void**)&y1,  g_y1);
    cudaGetSymbolAddress((void**)&y2,  g_y2);
    cudaGetSymbolAddress((void**)&y3,  g_y3);
    cudaGetSymbolAddress((void**)&w1r, g_w1r);
    cudaGetSymbolAddress((void**)&w2r, g_w2r);
    cudaGetSymbolAddress((void**)&w3r, g_w3r);
    cudaGetSymbolAddress((void**)&gsum, g_sum);
    cudaGetSymbolAddress((void**)&gsq,  g_sq);
    cudaGetSymbolAddress((void**)&bnS, g_bnS);
    cudaGetSymbolAddress((void**)&bnT, g_bnT);
    cudaGetSymbolAddress((void**)&goff, g_off);

    const double invN = 1.0 / ((double)B_ * (double)LOUT_);

    zero_stats<<<2, 256>>>(gsum, gsq);
    reorder_w<<<(128 * 4 * 8 + 255) / 256, 256>>>(w1, w1r, 128, 4, 8);
    reorder_w<<<(256 * 128 * 5 + 255) / 256, 256>>>(w2, w2r, 256, 128, 5);
    reorder_w<<<(128 * 256 * 3 + 255) / 256, 256>>>(w3, w3r, 128, 256, 3);

    dim3 gc1(3, 1, B_);
    conv_bn<true, 4, 128, 8, 4, 4><<<gc1, 256>>>(
        x, w1r, b1, nullptr, nullptr, y1, gsum, gsq, TIN, 0, LOUT_, LSTR_);
    finalize_bn<<<1, 256>>>(gsum, gsq, g1, be1, bnS, bnT, 128, invN);

    dim3 gc2(3, 2, B_);
    conv_bn<false, 128, 256, 5, 2, 8><<<gc2, 256>>>(
        y1, w2r, b2, bnS, bnT, y2, gsum + 128, gsq + 128, LOUT_, LSTR_, LOUT_, LSTR_);
    finalize_bn<<<1, 256>>>(gsum + 128, gsq + 128, g2, be2, bnS + 128, bnT + 128, 256, invN);

    dim3 gc3(3, 1, B_);
    conv_bn<false, 256, 128, 3, 1, 16><<<gc3, 256>>>(
        y2, w3r, b3, bnS + 128, bnT + 128, y3, gsum + 384, gsq + 384, LOUT_, LSTR_, LOUT_, LSTR_);
    finalize_bn<<<1, 256>>>(gsum + 384, gsq + 384, g3, be3, bnS + 384, bnT + 384, 128, invN);

    pool_fc_off<<<B_, 128>>>(y3, bnS + 384, bnT + 384, fcw, fcb, offw, offb, goff);
    dist_out<<<B_, 256>>>(x, mask, protos, goff, out);
}